// round 8
// baseline (speedup 1.0000x reference)
#include <cuda_runtime.h>
#include <cuda_fp16.h>
#include <math.h>
#include <stdint.h>

#define BATCH 8
#define CDIM 192
#define C3 576
#define HEADS 8
#define CHH 24
#define NPIX 16384
#define IMW 128

// ---------------- scratch (device globals; allocation-free rule) ------------
__device__ __half g_qkv1[BATCH * C3 * NPIX];     // after 1x1 conv (fp16)
__device__ __half g_qkv2[BATCH * C3 * NPIX];     // after dwconv (fp16)
__device__ float g_gram[BATCH * HEADS * CHH * CHH];
__device__ float g_nq[BATCH * CDIM];
__device__ float g_nk[BATCH * CDIM];
__device__ __half g_wq_hi[C3 * CDIM];
__device__ __half g_wq_lo[C3 * CDIM];
__device__ __half g_weff_hi[BATCH * CDIM * CDIM];
__device__ __half g_weff_lo[BATCH * CDIM * CDIM];

#define MMA_F16(d, a, bb) \
    asm volatile("mma.sync.aligned.m16n8k16.row.col.f32.f16.f16.f32 " \
        "{%0,%1,%2,%3}, {%4,%5,%6,%7}, {%8,%9}, {%0,%1,%2,%3};" \
        : "+f"((d)[0]), "+f"((d)[1]), "+f"((d)[2]), "+f"((d)[3]) \
        : "r"((a)[0]), "r"((a)[1]), "r"((a)[2]), "r"((a)[3]), \
          "r"((bb)[0]), "r"((bb)[1]))

#define LDSM_X4(r0, r1, r2, r3, addr) \
    asm volatile("ldmatrix.sync.aligned.m8n8.x4.shared.b16 {%0,%1,%2,%3}, [%4];" \
        : "=r"(r0), "=r"(r1), "=r"(r2), "=r"(r3) : "r"(addr))

__device__ __forceinline__ uint32_t pack_h2(__half a, __half b) {
    return ((uint32_t)__half_as_ushort(b) << 16) | __half_as_ushort(a);
}
__device__ __forceinline__ uint32_t smem_u32(const void* p) {
    uint32_t a;
    asm("{ .reg .u64 t; cvta.to.shared.u64 t, %1; cvt.u32.u64 %0, t; }"
        : "=r"(a) : "l"(p));
    return a;
}
__device__ __forceinline__ void cp_async16(uint32_t dst, const void* src) {
    asm volatile("cp.async.cg.shared.global [%0], [%1], 16;" :: "r"(dst), "l"(src));
}

// ---------------- B-type abstraction (fp32 input vs fp16 intermediate) -----
template <typename T> struct VecT;
template <> struct VecT<float>  { using t = float4; };
template <> struct VecT<__half> { using t = uint2;  };

#define LDB 40   // B row stride (halves)

__device__ __forceinline__ void ld_pb(float4& d, const float* p) {
    d = *reinterpret_cast<const float4*>(p);
}
__device__ __forceinline__ void ld_pb(uint2& d, const __half* p) {
    d = *reinterpret_cast<const uint2*>(p);
}
// store k-pair (rows kk, kk+1) for 4 consecutive n into [n][LDB] smem
__device__ __forceinline__ void st_b(__half* B, int nc, int kk,
                                     const float4& r0, const float4& r1) {
    float e0[4] = {r0.x, r0.y, r0.z, r0.w};
    float e1[4] = {r1.x, r1.y, r1.z, r1.w};
#pragma unroll
    for (int i = 0; i < 4; ++i)
        *reinterpret_cast<uint32_t*>(&B[(nc + i) * LDB + kk]) =
            pack_h2(__float2half(e0[i]), __float2half(e1[i]));
}
__device__ __forceinline__ void st_b(__half* B, int nc, int kk,
                                     const uint2& r0, const uint2& r1) {
    *reinterpret_cast<uint32_t*>(&B[(nc + 0) * LDB + kk]) = __byte_perm(r0.x, r1.x, 0x5410);
    *reinterpret_cast<uint32_t*>(&B[(nc + 1) * LDB + kk]) = __byte_perm(r0.x, r1.x, 0x7632);
    *reinterpret_cast<uint32_t*>(&B[(nc + 2) * LDB + kk]) = __byte_perm(r0.y, r1.y, 0x5410);
    *reinterpret_cast<uint32_t*>(&B[(nc + 3) * LDB + kk]) = __byte_perm(r0.y, r1.y, 0x7632);
}
__device__ __forceinline__ void st_out(float* p, float a, float b) {
    *reinterpret_cast<float2*>(p) = make_float2(a, b);
}
__device__ __forceinline__ void st_out(__half* p, float a, float b) {
    *reinterpret_cast<uint32_t*>(p) = pack_h2(__float2half(a), __float2half(b));
}

// ---------------------------------------------------------------------------
// HMMA GEMM (round-6 config): BM=192, BN=128, BK=32, K=192, 256 thr,
// 8 warps 4M x 2N (48x64/warp), 1 CTA/SM. W in fp16 hi/lo (2 MMA passes),
// B converted/copied into [n][k] smem, double-buffered; ldmatrix fragments.
// ---------------------------------------------------------------------------
#define LDAE 200
#define ALO_OFF (192 * LDAE * 2)
#define B0_OFF  (2 * 192 * LDAE * 2)
#define BBUF_BYTES (128 * LDB * 2)
#define SMEM_GEMM (B0_OFF + 2 * BBUF_BYTES)   // 174080

template <typename TB, typename TO>
__global__ __launch_bounds__(256, 1)
void gemm_mma(const __half* __restrict__ Whi,
              const __half* __restrict__ Wlo,
              long long wstride,
              const TB* __restrict__ X, long long xstride,
              TO* __restrict__ Y, long long ystride)
{
    extern __shared__ __half smem[];
    __half* Ah = smem;
    __half* Bb = reinterpret_cast<__half*>(reinterpret_cast<char*>(smem) + B0_OFF);

    const int b = blockIdx.z;
    const int o0 = blockIdx.x * 192;
    const int n0 = blockIdx.y * 128;
    const __half* Wh = Whi + (long long)b * wstride;
    const __half* Wl = Wlo + (long long)b * wstride;
    const TB* Xp = X + (long long)b * xstride;
    TO* Yp = Y + (long long)b * ystride;

    const int tid = threadIdx.x;
    const int lane = tid & 31;
    const int wid = tid >> 5;
    const int wm = wid & 3;
    const int wn = wid >> 2;

    // ---- async load of full A (hi + lo) ----
    {
        const uint32_t ah = smem_u32(Ah);
#pragma unroll
        for (int c = 0; c < 18; ++c) {
            int ch = c * 256 + tid;
            int row = ch / 24, col = ch % 24;
            uint32_t doff = (uint32_t)(row * LDAE + col * 8) * 2u;
            long long soff = (long long)(o0 + row) * CDIM + col * 8;
            cp_async16(ah + doff, Wh + soff);
            cp_async16(ah + ALO_OFF + doff, Wl + soff);
        }
        asm volatile("cp.async.commit_group;");
    }

    float acc[3][8][4];
#pragma unroll
    for (int mi = 0; mi < 3; ++mi)
#pragma unroll
        for (int ni = 0; ni < 8; ++ni)
#pragma unroll
            for (int q = 0; q < 4; ++q) acc[mi][ni][q] = 0.f;

    // ---- ldmatrix per-lane addresses ----
    const int lg = lane >> 3, lr = lane & 7;
    const uint32_t a_base = smem_u32(Ah);
    const uint32_t b_base = smem_u32(Bb);
    uint32_t a_row[3];
#pragma unroll
    for (int mi = 0; mi < 3; ++mi) {
        int row = wm * 48 + mi * 16 + (lg & 1) * 8 + lr;
        a_row[mi] = a_base + (uint32_t)(row * LDAE + (lg >> 1) * 8) * 2u;
    }
    uint32_t b_row[4];
#pragma unroll
    for (int nj = 0; nj < 4; ++nj) {
        int n = wn * 64 + (nj * 2 + (lg >> 1)) * 8 + lr;
        b_row[nj] = (uint32_t)(n * LDB + (lg & 1) * 8) * 2u;
    }

    // ---- B prefetch: thread covers rows {kr, kr+1} x {0,16} and 4 n's ----
    const int kr = (tid >> 5) * 2;
    const int nc = (tid & 31) * 4;
    typename VecT<TB>::t pb[2][2];
#pragma unroll
    for (int j = 0; j < 2; ++j)
#pragma unroll
        for (int r = 0; r < 2; ++r)
            ld_pb(pb[j][r], &Xp[(long long)(j * 16 + kr + r) * NPIX + n0 + nc]);

    asm volatile("cp.async.wait_group 0;");
#pragma unroll
    for (int j = 0; j < 2; ++j)
        st_b(Bb, nc, j * 16 + kr, pb[j][0], pb[j][1]);
    __syncthreads();

    for (int kt = 0; kt < 6; ++kt) {
        const uint32_t cur_off = (uint32_t)(kt & 1) * BBUF_BYTES;
        const uint32_t nxt_off = BBUF_BYTES - cur_off;

        if (kt < 5) {
#pragma unroll
            for (int j = 0; j < 2; ++j)
#pragma unroll
                for (int r = 0; r < 2; ++r)
                    ld_pb(pb[j][r],
                          &Xp[(long long)((kt + 1) * 32 + j * 16 + kr + r) * NPIX + n0 + nc]);
        }

#pragma unroll
        for (int ks = 0; ks < 2; ++ks) {
            const uint32_t akoff = (uint32_t)(kt * 32 + ks * 16) * 2u;
            const uint32_t bkoff = (uint32_t)(ks * 16) * 2u;
            uint32_t fah[3][4], fal[3][4], fb[8][2];
#pragma unroll
            for (int mi = 0; mi < 3; ++mi) {
                LDSM_X4(fah[mi][0], fah[mi][1], fah[mi][2], fah[mi][3],
                        a_row[mi] + akoff);
                LDSM_X4(fal[mi][0], fal[mi][1], fal[mi][2], fal[mi][3],
                        a_row[mi] + akoff + ALO_OFF);
            }
#pragma unroll
            for (int nj = 0; nj < 4; ++nj) {
                LDSM_X4(fb[2 * nj][0], fb[2 * nj][1], fb[2 * nj + 1][0], fb[2 * nj + 1][1],
                        b_base + cur_off + b_row[nj] + bkoff);
            }
#pragma unroll
            for (int mi = 0; mi < 3; ++mi)
#pragma unroll
                for (int ni = 0; ni < 8; ++ni) {
                    MMA_F16(acc[mi][ni], fah[mi], fb[ni]);
                    MMA_F16(acc[mi][ni], fal[mi], fb[ni]);
                }
        }

        if (kt < 5) {
            __half* Bn = reinterpret_cast<__half*>(
                reinterpret_cast<char*>(Bb) + nxt_off);
#pragma unroll
            for (int j = 0; j < 2; ++j)
                st_b(Bn, nc, j * 16 + kr, pb[j][0], pb[j][1]);
        }
        __syncthreads();
    }

    // ---- epilogue ----
#pragma unroll
    for (int mi = 0; mi < 3; ++mi) {
        int r = o0 + wm * 48 + mi * 16 + (lane >> 2);
#pragma unroll
        for (int ni = 0; ni < 8; ++ni) {
            int c = n0 + wn * 64 + ni * 8 + (lane & 3) * 2;
            st_out(&Yp[(long long)r * NPIX + c], acc[mi][ni][0], acc[mi][ni][1]);
            st_out(&Yp[(long long)(r + 8) * NPIX + c], acc[mi][ni][2], acc[mi][ni][3]);
        }
    }
}

// ---------------------------------------------------------------------------
// Weight prep: fp32 -> fp16 hi/lo (two launches to keep gemm1 at ncu slot 4)
// ---------------------------------------------------------------------------
__global__ void prep_wqkv_kernel(const float* __restrict__ W, int base)
{
    int idx = base + blockIdx.x * blockDim.x + threadIdx.x;
    if (idx >= C3 * CDIM) return;
    float v = W[idx];
    __half h = __float2half(v);
    g_wq_hi[idx] = h;
    g_wq_lo[idx] = __float2half(v - __half2float(h));
}

// ---------------------------------------------------------------------------
// 3x3 depthwise conv, padding 1; fp16 in/out, fp32 math; 4 px/thread
// ---------------------------------------------------------------------------
__global__ void dwconv_kernel(const __half* __restrict__ in,
                              const float* __restrict__ wdw,
                              __half* __restrict__ out)
{
    long long idx = (long long)blockIdx.x * blockDim.x + threadIdx.x;
    if (idx >= (long long)BATCH * C3 * (NPIX / 4)) return;
    const int n4 = (int)(idx & (NPIX / 4 - 1));
    const int ch = (int)(idx >> 12);
    const int oc = ch % C3;
    const int y = n4 >> 5;
    const int x0 = (n4 & 31) * 4;
    const float* w = wdw + oc * 9;
    const __half* p = in + (long long)ch * NPIX;

    float o0 = 0.f, o1 = 0.f, o2 = 0.f, o3 = 0.f;
#pragma unroll
    for (int r = 0; r < 3; ++r) {
        int yy = y + r - 1;
        if (yy < 0 || yy > IMW - 1) continue;
        const __half* row = p + yy * IMW;
        float2 cab = __half22float2(*reinterpret_cast<const __half2*>(&row[x0]));
        float2 ccd = __half22float2(*reinterpret_cast<const __half2*>(&row[x0 + 2]));
        float lft = (x0 > 0) ? __half2float(row[x0 - 1]) : 0.f;
        float rgt = (x0 < IMW - 4) ? __half2float(row[x0 + 4]) : 0.f;
        float w0 = w[r * 3], w1 = w[r * 3 + 1], w2 = w[r * 3 + 2];
        o0 += w0 * lft   + w1 * cab.x + w2 * cab.y;
        o1 += w0 * cab.x + w1 * cab.y + w2 * ccd.x;
        o2 += w0 * cab.y + w1 * ccd.x + w2 * ccd.y;
        o3 += w0 * ccd.x + w1 * ccd.y + w2 * rgt;
    }
    uint2 res;
    res.x = pack_h2(__float2half(o0), __float2half(o1));
    res.y = pack_h2(__float2half(o2), __float2half(o3));
    *reinterpret_cast<uint2*>(&out[(long long)ch * NPIX + y * IMW + x0]) = res;
}

__global__ void zero_misc_kernel()
{
    int i = blockIdx.x * blockDim.x + threadIdx.x;
    if (i < BATCH * HEADS * CHH * CHH) g_gram[i] = 0.f;
    if (i < BATCH * CDIM) { g_nq[i] = 0.f; g_nk[i] = 0.f; }
}

// ---------------------------------------------------------------------------
// Gram + fused norms (q,k fp16; feat fp32; fp32 accumulate)
// ---------------------------------------------------------------------------
__global__ void gram_kernel(const float* __restrict__ feat)
{
    __shared__ float QF[4][CHH][64];
    __shared__ float KF[4][CHH][64];

    const int bh = blockIdx.y;
    const int b = bh >> 3, hd = bh & 7;
    const int n0 = blockIdx.x * 1024;
    const int t = threadIdx.x;
    const int g = t >> 6, l = t & 63;
    const int li = l >> 3, lj = l & 7;
    const int i0 = li * 3, j0 = lj * 3;

    const __half* qbase = g_qkv2 + ((long long)b * C3 + hd * CHH) * NPIX;
    const __half* kbase = g_qkv2 + ((long long)b * C3 + CDIM + hd * CHH) * NPIX;
    const float* fbase = feat + ((long long)b * CDIM + hd * CHH) * NPIX;

    float acc[3][3];
#pragma unroll
    for (int a = 0; a < 3; ++a)
#pragma unroll
        for (int cc = 0; cc < 3; ++cc) acc[a][cc] = 0.f;
    float nqp = 0.f, nkp = 0.f;

    for (int s = 0; s < 1024; s += 256) {
        const int nb = n0 + s + g * 64;
        for (int e = l; e < CHH * 64; e += 64) {
            int i = e >> 6, nn = e & 63;
            long long off = (long long)i * NPIX + nb + nn;
            float fv = fbase[off];
            QF[g][i][nn] = __half2float(qbase[off]) * fv;
            KF[g][i][nn] = __half2float(kbase[off]) * fv;
        }
        __syncthreads();
#pragma unroll 4
        for (int it = 0; it < 64; ++it) {
            int nn = (it + l) & 63;
            float q0 = QF[g][i0 + 0][nn];
            float q1 = QF[g][i0 + 1][nn];
            float q2 = QF[g][i0 + 2][nn];
            float k0 = KF[g][j0 + 0][nn];
            float k1 = KF[g][j0 + 1][nn];
            float k2 = KF[g][j0 + 2][nn];
            acc[0][0] += q0 * k0; acc[0][1] += q0 * k1; acc[0][2] += q0 * k2;
            acc[1][0] += q1 * k0; acc[1][1] += q1 * k1; acc[1][2] += q1 * k2;
            acc[2][0] += q2 * k0; acc[2][1] += q2 * k1; acc[2][2] += q2 * k2;
        }
        if (l < CHH) {
#pragma unroll 4
            for (int it = 0; it < 64; ++it) {
                int nn = (it + l) & 63;
                float qv = QF[g][l][nn]; nqp += qv * qv;
                float kv = KF[g][l][nn]; nkp += kv * kv;
            }
        }
        __syncthreads();
    }

#pragma unroll
    for (int a = 0; a < 3; ++a)
#pragma unroll
        for (int cc = 0; cc < 3; ++cc)
            atomicAdd(&g_gram[(bh * CHH + i0 + a) * CHH + j0 + cc], acc[a][cc]);
    if (l < CHH) {
        atomicAdd(&g_nq[b * CDIM + hd * CHH + l], nqp);
        atomicAdd(&g_nk[b * CDIM + hd * CHH + l], nkp);
    }
}

// ---------------------------------------------------------------------------
// Softmax + W_eff = W_proj @ A_blockdiag, emitted fp16 hi/lo [192][192]
// ---------------------------------------------------------------------------
__global__ void softmax_weff_kernel(const float* __restrict__ temp,
                                    const float* __restrict__ Wp)
{
    const int b = blockIdx.x;
    const int t = threadIdx.x;            // 384
    __shared__ float A[HEADS][CHH][CHH];
    __shared__ float qinv[CDIM], kinv[CDIM];

    if (t < CDIM) {
        qinv[t] = 1.0f / fmaxf(sqrtf(g_nq[b * CDIM + t]), 1e-12f);
    } else if (t < 2 * CDIM) {
        int c = t - CDIM;
        kinv[c] = 1.0f / fmaxf(sqrtf(g_nk[b * CDIM + c]), 1e-12f);
    }
    __syncthreads();

    if (t < CDIM) {
        const int hd = t / CHH, i = t % CHH;
        const float tp = temp[hd];
        const float qi = qinv[hd * CHH + i];
        float row[CHH];
        float m = -1e30f;
#pragma unroll
        for (int j = 0; j < CHH; ++j) {
            float v = g_gram[((b * HEADS + hd) * CHH + i) * CHH + j]
                      * tp * qi * kinv[hd * CHH + j];
            row[j] = v;
            m = fmaxf(m, v);
        }
        float ssum = 0.f;
#pragma unroll
        for (int j = 0; j < CHH; ++j) { row[j] = expf(row[j] - m); ssum += row[j]; }
        float inv = 1.0f / ssum;
#pragma unroll
        for (int j = 0; j < CHH; ++j) A[hd][i][j] = row[j] * inv;
    }
    __syncthreads();

    for (int idx = t; idx < CDIM * CDIM; idx += 384) {
        const int o = idx / CDIM, cc = idx % CDIM;
        const int hd = cc / CHH, j = cc % CHH;
        float s = 0.f;
#pragma unroll
        for (int i = 0; i < CHH; ++i)
            s += Wp[o * CDIM + hd * CHH + i] * A[hd][i][j];
        __half h = __float2half(s);
        g_weff_hi[(long long)b * CDIM * CDIM + idx] = h;
        g_weff_lo[(long long)b * CDIM * CDIM + idx] =
            __float2half(s - __half2float(h));
    }
}

// ---------------------------------------------------------------------------
extern "C" void kernel_launch(void* const* d_in, const int* in_sizes, int n_in,
                              void* d_out, int out_size)
{
    (void)in_sizes; (void)n_in; (void)out_size;
    const float* x     = (const float*)d_in[0];
    const float* feat  = (const float*)d_in[1];
    const float* Wqkv  = (const float*)d_in[2];
    const float* Wdw   = (const float*)d_in[3];
    const float* Wproj = (const float*)d_in[4];
    const float* temp  = (const float*)d_in[5];
    float* out = (float*)d_out;

    __half *qkv1, *qkv2, *wqh, *wql, *wfh, *wfl;
    cudaGetSymbolAddress((void**)&qkv1, g_qkv1);
    cudaGetSymbolAddress((void**)&qkv2, g_qkv2);
    cudaGetSymbolAddress((void**)&wqh, g_wq_hi);
    cudaGetSymbolAddress((void**)&wql, g_wq_lo);
    cudaGetSymbolAddress((void**)&wfh, g_weff_hi);
    cudaGetSymbolAddress((void**)&wfl, g_weff_lo);

    static int smem_set = 0;
    if (!smem_set) {
        cudaFuncSetAttribute(gemm_mma<float, __half>,
                             cudaFuncAttributeMaxDynamicSharedMemorySize, SMEM_GEMM);
        cudaFuncSetAttribute(gemm_mma<__half, float>,
                             cudaFuncAttributeMaxDynamicSharedMemorySize, SMEM_GEMM);
        smem_set = 1;
    }

    const int HALF_W = C3 * CDIM / 2;

    // Launch order keeps gemm1 at ncu slot 4.
    zero_misc_kernel<<<(BATCH * HEADS * CHH * CHH + 255) / 256, 256>>>();
    prep_wqkv_kernel<<<(HALF_W + 255) / 256, 256>>>(Wqkv, 0);
    prep_wqkv_kernel<<<(HALF_W + 255) / 256, 256>>>(Wqkv, HALF_W);

    // 4) qkv1 = W_qkv @ x   (fp32 B in, fp16 out)
    gemm_mma<float, __half><<<dim3(3, NPIX / 128, BATCH), 256, SMEM_GEMM>>>(
        wqh, wql, 0LL, x, (long long)CDIM * NPIX, qkv1, (long long)C3 * NPIX);

    // 5) depthwise conv (fp16 in/out)
    {
        long long total = (long long)BATCH * C3 * (NPIX / 4);
        dwconv_kernel<<<(int)((total + 255) / 256), 256>>>(qkv1, Wdw, qkv2);
    }

    // 6) Gram + norms
    gram_kernel<<<dim3(16, BATCH * HEADS), 256>>>(feat);

    // 7) softmax + W_eff
    softmax_weff_kernel<<<BATCH, 384>>>(temp, Wproj);

    // 8) out = W_eff @ v   (fp16 B in, fp32 out)
    gemm_mma<__half, float><<<dim3(1, NPIX / 128, BATCH), 256, SMEM_GEMM>>>(
        wfh, wfl, (long long)CDIM * CDIM,
        qkv2 + (long long)2 * CDIM * NPIX, (long long)C3 * NPIX,
        out, (long long)CDIM * NPIX);
}

// round 9
// speedup vs baseline: 1.3064x; 1.3064x over previous
#include <cuda_runtime.h>
#include <cuda_fp16.h>
#include <math.h>
#include <stdint.h>

#define BATCH 8
#define CDIM 192
#define C3 576
#define HEADS 8
#define CHH 24
#define NPIX 16384
#define IMW 128

// ---------------- scratch (device globals; allocation-free rule) ------------
__device__ float g_qkv1[BATCH * C3 * NPIX];
__device__ float g_qkv2[BATCH * C3 * NPIX];
__device__ float g_gram[BATCH * HEADS * CHH * CHH];
__device__ float g_nq[BATCH * CDIM];
__device__ float g_nk[BATCH * CDIM];
__device__ __half g_wq[C3 * CDIM];
__device__ __half g_weff[BATCH * CDIM * CDIM];

#define MMA_F16(d, a, bb) \
    asm volatile("mma.sync.aligned.m16n8k16.row.col.f32.f16.f16.f32 " \
        "{%0,%1,%2,%3}, {%4,%5,%6,%7}, {%8,%9}, {%0,%1,%2,%3};" \
        : "+f"((d)[0]), "+f"((d)[1]), "+f"((d)[2]), "+f"((d)[3]) \
        : "r"((a)[0]), "r"((a)[1]), "r"((a)[2]), "r"((a)[3]), \
          "r"((bb)[0]), "r"((bb)[1]))

#define LDSM_X4(r0, r1, r2, r3, addr) \
    asm volatile("ldmatrix.sync.aligned.m8n8.x4.shared.b16 {%0,%1,%2,%3}, [%4];" \
        : "=r"(r0), "=r"(r1), "=r"(r2), "=r"(r3) : "r"(addr))

__device__ __forceinline__ uint32_t pack_h2(__half a, __half b) {
    return ((uint32_t)__half_as_ushort(b) << 16) | __half_as_ushort(a);
}
__device__ __forceinline__ uint32_t smem_u32(const void* p) {
    uint32_t a;
    asm("{ .reg .u64 t; cvta.to.shared.u64 t, %1; cvt.u32.u64 %0, t; }"
        : "=r"(a) : "l"(p));
    return a;
}
__device__ __forceinline__ void cp_async16(uint32_t dst, const void* src) {
    asm volatile("cp.async.cg.shared.global [%0], [%1], 16;" :: "r"(dst), "l"(src));
}

// ---------------------------------------------------------------------------
// HMMA GEMM: Y[o,n] = sum_c W[o,c] X[c,n] per batch. Single fp16 W pass.
// BM=192, BN=64, BK=32, K=192. 256 threads (8 warps: 4M x 2N; 48x32/warp).
// 2 CTAs/SM. Full A resident in SMEM (cp.async once); B double-buffered,
// fp32->fp16 converted in-flight; fragments via ldmatrix.x4.
// ---------------------------------------------------------------------------
#define LDAE 200                       // A row stride (halves)
#define LDB  40                        // B row stride (halves)
#define B0_OFF  (192 * LDAE * 2)       // bytes: B buffer 0 (76800)
#define BBUF_BYTES (64 * LDB * 2)      // 5120
#define SMEM_GEMM (B0_OFF + 2 * BBUF_BYTES)   // 87040 bytes

__global__ __launch_bounds__(256, 2)
void gemm_mma(const __half* __restrict__ W, long long wstride,
              const float* __restrict__ X, long long xstride,
              float* __restrict__ Y, long long ystride)
{
    extern __shared__ __half smem[];
    __half* Ah = smem;
    __half* Bb = reinterpret_cast<__half*>(reinterpret_cast<char*>(smem) + B0_OFF);

    const int b = blockIdx.z;
    const int o0 = blockIdx.x * 192;
    const int n0 = blockIdx.y * 64;
    const __half* Wp = W + (long long)b * wstride;
    const float* Xp = X + (long long)b * xstride;
    float* Yp = Y + (long long)b * ystride;

    const int tid = threadIdx.x;
    const int lane = tid & 31;
    const int wid = tid >> 5;
    const int wm = wid & 3;            // 4 in M (48 rows each)
    const int wn = wid >> 2;           // 2 in N (32 cols each)

    // ---- async load of full A: 192 rows x 192 k ----
    {
        const uint32_t ah = smem_u32(Ah);
#pragma unroll
        for (int c = 0; c < 18; ++c) {
            int ch = c * 256 + tid;            // 0..4607
            int row = ch / 24, col = ch % 24;  // 16B chunks (8 halves)
            uint32_t doff = (uint32_t)(row * LDAE + col * 8) * 2u;
            long long soff = (long long)(o0 + row) * CDIM + col * 8;
            cp_async16(ah + doff, Wp + soff);
        }
        asm volatile("cp.async.commit_group;");
    }

    float acc[3][4][4];
#pragma unroll
    for (int mi = 0; mi < 3; ++mi)
#pragma unroll
        for (int ni = 0; ni < 4; ++ni)
#pragma unroll
            for (int q = 0; q < 4; ++q) acc[mi][ni][q] = 0.f;

    // ---- ldmatrix per-lane addresses ----
    const int lg = lane >> 3, lr = lane & 7;
    const uint32_t a_base = smem_u32(Ah);
    const uint32_t b_base = smem_u32(Bb);
    uint32_t a_row[3];
#pragma unroll
    for (int mi = 0; mi < 3; ++mi) {
        int row = wm * 48 + mi * 16 + (lg & 1) * 8 + lr;
        a_row[mi] = a_base + (uint32_t)(row * LDAE + (lg >> 1) * 8) * 2u;
    }
    uint32_t b_row[2];
#pragma unroll
    for (int nj = 0; nj < 2; ++nj) {
        int n = wn * 32 + (nj * 2 + (lg >> 1)) * 8 + lr;
        b_row[nj] = (uint32_t)(n * LDB + (lg & 1) * 8) * 2u;
    }

    // ---- B conversion lane mapping: thread covers k rows {kr,kr+1}, 4 n ----
    const int kr = (tid >> 4) * 2;        // 0..30 even
    const int nc = (tid & 15) * 4;        // n within tile
    float4 pb[2];
#pragma unroll
    for (int r = 0; r < 2; ++r)
        pb[r] = *reinterpret_cast<const float4*>(
            &Xp[(long long)(kr + r) * NPIX + n0 + nc]);

    // prologue: convert tile 0 into buffer 0
    asm volatile("cp.async.wait_group 0;");
    {
        float e0[4] = {pb[0].x, pb[0].y, pb[0].z, pb[0].w};
        float e1[4] = {pb[1].x, pb[1].y, pb[1].z, pb[1].w};
#pragma unroll
        for (int i = 0; i < 4; ++i)
            *reinterpret_cast<uint32_t*>(&Bb[(nc + i) * LDB + kr]) =
                pack_h2(__float2half(e0[i]), __float2half(e1[i]));
    }
    __syncthreads();

    for (int kt = 0; kt < 6; ++kt) {
        const uint32_t cur_off = (uint32_t)(kt & 1) * BBUF_BYTES;
        const uint32_t nxt_off = BBUF_BYTES - cur_off;

        // ---- prefetch next tile from gmem ----
        if (kt < 5) {
#pragma unroll
            for (int r = 0; r < 2; ++r)
                pb[r] = *reinterpret_cast<const float4*>(
                    &Xp[(long long)((kt + 1) * 32 + kr + r) * NPIX + n0 + nc]);
        }

        // ---- compute 2 ksteps from current buffer ----
#pragma unroll
        for (int ks = 0; ks < 2; ++ks) {
            const uint32_t akoff = (uint32_t)(kt * 32 + ks * 16) * 2u;
            const uint32_t bkoff = (uint32_t)(ks * 16) * 2u;
            uint32_t fa[3][4], fb[4][2];
#pragma unroll
            for (int mi = 0; mi < 3; ++mi)
                LDSM_X4(fa[mi][0], fa[mi][1], fa[mi][2], fa[mi][3],
                        a_row[mi] + akoff);
#pragma unroll
            for (int nj = 0; nj < 2; ++nj)
                LDSM_X4(fb[2 * nj][0], fb[2 * nj][1], fb[2 * nj + 1][0], fb[2 * nj + 1][1],
                        b_base + cur_off + b_row[nj] + bkoff);
#pragma unroll
            for (int mi = 0; mi < 3; ++mi)
#pragma unroll
                for (int ni = 0; ni < 4; ++ni)
                    MMA_F16(acc[mi][ni], fa[mi], fb[ni]);
        }

        // ---- convert prefetched tile into the other buffer ----
        if (kt < 5) {
            __half* Bn = reinterpret_cast<__half*>(
                reinterpret_cast<char*>(Bb) + nxt_off);
            float e0[4] = {pb[0].x, pb[0].y, pb[0].z, pb[0].w};
            float e1[4] = {pb[1].x, pb[1].y, pb[1].z, pb[1].w};
#pragma unroll
            for (int i = 0; i < 4; ++i)
                *reinterpret_cast<uint32_t*>(&Bn[(nc + i) * LDB + kr]) =
                    pack_h2(__float2half(e0[i]), __float2half(e1[i]));
        }
        __syncthreads();
    }

    // ---- epilogue ----
#pragma unroll
    for (int mi = 0; mi < 3; ++mi) {
        int r = o0 + wm * 48 + mi * 16 + (lane >> 2);
#pragma unroll
        for (int ni = 0; ni < 4; ++ni) {
            int c = n0 + wn * 32 + ni * 8 + (lane & 3) * 2;
            *reinterpret_cast<float2*>(&Yp[(long long)r * NPIX + c]) =
                make_float2(acc[mi][ni][0], acc[mi][ni][1]);
            *reinterpret_cast<float2*>(&Yp[(long long)(r + 8) * NPIX + c]) =
                make_float2(acc[mi][ni][2], acc[mi][ni][3]);
        }
    }
}

// ---------------------------------------------------------------------------
// Weight prep: fp32 -> fp16 (two launches keep gemm1 at ncu slot 4)
// ---------------------------------------------------------------------------
__global__ void prep_wqkv_kernel(const float* __restrict__ W, int base)
{
    int idx = base + blockIdx.x * blockDim.x + threadIdx.x;
    if (idx >= C3 * CDIM) return;
    g_wq[idx] = __float2half(W[idx]);
}

// ---------------------------------------------------------------------------
// 3x3 depthwise conv, padding 1; 4 pixels per thread (float4)
// ---------------------------------------------------------------------------
__global__ void dwconv_kernel(const float* __restrict__ in,
                              const float* __restrict__ wdw,
                              float* __restrict__ out)
{
    long long idx = (long long)blockIdx.x * blockDim.x + threadIdx.x;
    if (idx >= (long long)BATCH * C3 * (NPIX / 4)) return;
    const int n4 = (int)(idx & (NPIX / 4 - 1));
    const int ch = (int)(idx >> 12);
    const int oc = ch % C3;
    const int y = n4 >> 5;
    const int x0 = (n4 & 31) * 4;
    const float* w = wdw + oc * 9;
    const float* p = in + (long long)ch * NPIX;

    float4 o = make_float4(0.f, 0.f, 0.f, 0.f);
#pragma unroll
    for (int r = 0; r < 3; ++r) {
        int yy = y + r - 1;
        if (yy < 0 || yy > IMW - 1) continue;
        const float* row = p + yy * IMW;
        float4 c = *reinterpret_cast<const float4*>(&row[x0]);
        float lft = (x0 > 0) ? row[x0 - 1] : 0.f;
        float rgt = (x0 < IMW - 4) ? row[x0 + 4] : 0.f;
        float w0 = w[r * 3], w1 = w[r * 3 + 1], w2 = w[r * 3 + 2];
        o.x += w0 * lft + w1 * c.x + w2 * c.y;
        o.y += w0 * c.x + w1 * c.y + w2 * c.z;
        o.z += w0 * c.y + w1 * c.z + w2 * c.w;
        o.w += w0 * c.z + w1 * c.w + w2 * rgt;
    }
    *reinterpret_cast<float4*>(&out[(long long)ch * NPIX + y * IMW + x0]) = o;
}

__global__ void zero_misc_kernel()
{
    int i = blockIdx.x * blockDim.x + threadIdx.x;
    if (i < BATCH * HEADS * CHH * CHH) g_gram[i] = 0.f;
    if (i < BATCH * CDIM) { g_nq[i] = 0.f; g_nk[i] = 0.f; }
}

// ---------------------------------------------------------------------------
// Gram + fused norms
// ---------------------------------------------------------------------------
__global__ void gram_kernel(const float* __restrict__ feat)
{
    __shared__ float QF[4][CHH][64];
    __shared__ float KF[4][CHH][64];

    const int bh = blockIdx.y;
    const int b = bh >> 3, hd = bh & 7;
    const int n0 = blockIdx.x * 1024;
    const int t = threadIdx.x;
    const int g = t >> 6, l = t & 63;
    const int li = l >> 3, lj = l & 7;
    const int i0 = li * 3, j0 = lj * 3;

    const float* qbase = g_qkv2 + ((long long)b * C3 + hd * CHH) * NPIX;
    const float* kbase = g_qkv2 + ((long long)b * C3 + CDIM + hd * CHH) * NPIX;
    const float* fbase = feat + ((long long)b * CDIM + hd * CHH) * NPIX;

    float acc[3][3];
#pragma unroll
    for (int a = 0; a < 3; ++a)
#pragma unroll
        for (int cc = 0; cc < 3; ++cc) acc[a][cc] = 0.f;
    float nqp = 0.f, nkp = 0.f;

    for (int s = 0; s < 1024; s += 256) {
        const int nb = n0 + s + g * 64;
        for (int e = l; e < CHH * 64; e += 64) {
            int i = e >> 6, nn = e & 63;
            long long off = (long long)i * NPIX + nb + nn;
            float fv = fbase[off];
            QF[g][i][nn] = qbase[off] * fv;
            KF[g][i][nn] = kbase[off] * fv;
        }
        __syncthreads();
#pragma unroll 4
        for (int it = 0; it < 64; ++it) {
            int nn = (it + l) & 63;
            float q0 = QF[g][i0 + 0][nn];
            float q1 = QF[g][i0 + 1][nn];
            float q2 = QF[g][i0 + 2][nn];
            float k0 = KF[g][j0 + 0][nn];
            float k1 = KF[g][j0 + 1][nn];
            float k2 = KF[g][j0 + 2][nn];
            acc[0][0] += q0 * k0; acc[0][1] += q0 * k1; acc[0][2] += q0 * k2;
            acc[1][0] += q1 * k0; acc[1][1] += q1 * k1; acc[1][2] += q1 * k2;
            acc[2][0] += q2 * k0; acc[2][1] += q2 * k1; acc[2][2] += q2 * k2;
        }
        if (l < CHH) {
#pragma unroll 4
            for (int it = 0; it < 64; ++it) {
                int nn = (it + l) & 63;
                float qv = QF[g][l][nn]; nqp += qv * qv;
                float kv = KF[g][l][nn]; nkp += kv * kv;
            }
        }
        __syncthreads();
    }

#pragma unroll
    for (int a = 0; a < 3; ++a)
#pragma unroll
        for (int cc = 0; cc < 3; ++cc)
            atomicAdd(&g_gram[(bh * CHH + i0 + a) * CHH + j0 + cc], acc[a][cc]);
    if (l < CHH) {
        atomicAdd(&g_nq[b * CDIM + hd * CHH + l], nqp);
        atomicAdd(&g_nk[b * CDIM + hd * CHH + l], nkp);
    }
}

// ---------------------------------------------------------------------------
// Softmax + W_eff = W_proj @ A_blockdiag, emitted single fp16 [192][192]
// ---------------------------------------------------------------------------
__global__ void softmax_weff_kernel(const float* __restrict__ temp,
                                    const float* __restrict__ Wp)
{
    const int b = blockIdx.x;
    const int t = threadIdx.x;            // 384
    __shared__ float A[HEADS][CHH][CHH];
    __shared__ float qinv[CDIM], kinv[CDIM];

    if (t < CDIM) {
        qinv[t] = 1.0f / fmaxf(sqrtf(g_nq[b * CDIM + t]), 1e-12f);
    } else if (t < 2 * CDIM) {
        int c = t - CDIM;
        kinv[c] = 1.0f / fmaxf(sqrtf(g_nk[b * CDIM + c]), 1e-12f);
    }
    __syncthreads();

    if (t < CDIM) {
        const int hd = t / CHH, i = t % CHH;
        const float tp = temp[hd];
        const float qi = qinv[hd * CHH + i];
        float row[CHH];
        float m = -1e30f;
#pragma unroll
        for (int j = 0; j < CHH; ++j) {
            float v = g_gram[((b * HEADS + hd) * CHH + i) * CHH + j]
                      * tp * qi * kinv[hd * CHH + j];
            row[j] = v;
            m = fmaxf(m, v);
        }
        float ssum = 0.f;
#pragma unroll
        for (int j = 0; j < CHH; ++j) { row[j] = expf(row[j] - m); ssum += row[j]; }
        float inv = 1.0f / ssum;
#pragma unroll
        for (int j = 0; j < CHH; ++j) A[hd][i][j] = row[j] * inv;
    }
    __syncthreads();

    for (int idx = t; idx < CDIM * CDIM; idx += 384) {
        const int o = idx / CDIM, cc = idx % CDIM;
        const int hd = cc / CHH, j = cc % CHH;
        float s = 0.f;
#pragma unroll
        for (int i = 0; i < CHH; ++i)
            s += Wp[o * CDIM + hd * CHH + i] * A[hd][i][j];
        g_weff[(long long)b * CDIM * CDIM + idx] = __float2half(s);
    }
}

// ---------------------------------------------------------------------------
extern "C" void kernel_launch(void* const* d_in, const int* in_sizes, int n_in,
                              void* d_out, int out_size)
{
    (void)in_sizes; (void)n_in; (void)out_size;
    const float* x     = (const float*)d_in[0];
    const float* feat  = (const float*)d_in[1];
    const float* Wqkv  = (const float*)d_in[2];
    const float* Wdw   = (const float*)d_in[3];
    const float* Wproj = (const float*)d_in[4];
    const float* temp  = (const float*)d_in[5];
    float* out = (float*)d_out;

    float *qkv1, *qkv2;
    __half *wq, *wf;
    cudaGetSymbolAddress((void**)&qkv1, g_qkv1);
    cudaGetSymbolAddress((void**)&qkv2, g_qkv2);
    cudaGetSymbolAddress((void**)&wq, g_wq);
    cudaGetSymbolAddress((void**)&wf, g_weff);

    static int smem_set = 0;
    if (!smem_set) {
        cudaFuncSetAttribute(gemm_mma, cudaFuncAttributeMaxDynamicSharedMemorySize,
                             SMEM_GEMM);
        smem_set = 1;
    }

    const int HALF_W = C3 * CDIM / 2;

    // Launch order keeps gemm1 at ncu slot 4.
    zero_misc_kernel<<<(BATCH * HEADS * CHH * CHH + 255) / 256, 256>>>();
    prep_wqkv_kernel<<<(HALF_W + 255) / 256, 256>>>(Wqkv, 0);
    prep_wqkv_kernel<<<(HALF_W + 255) / 256, 256>>>(Wqkv, HALF_W);

    // 4) qkv1 = W_qkv @ x
    gemm_mma<<<dim3(3, NPIX / 64, BATCH), 256, SMEM_GEMM>>>(
        wq, 0LL, x, (long long)CDIM * NPIX, qkv1, (long long)C3 * NPIX);

    // 5) depthwise conv
    {
        long long total = (long long)BATCH * C3 * (NPIX / 4);
        dwconv_kernel<<<(int)((total + 255) / 256), 256>>>(qkv1, Wdw, qkv2);
    }

    // 6) Gram + norms
    gram_kernel<<<dim3(16, BATCH * HEADS), 256>>>(feat);

    // 7) softmax + W_eff (fp16)
    softmax_weff_kernel<<<BATCH, 384>>>(temp, Wproj);

    // 8) out = W_eff @ v
    gemm_mma<<<dim3(1, NPIX / 64, BATCH), 256, SMEM_GEMM>>>(
        wf, (long long)CDIM * CDIM,
        qkv2 + (long long)2 * CDIM * NPIX, (long long)C3 * NPIX,
        out, (long long)CDIM * NPIX);
}